// round 1
// baseline (speedup 1.0000x reference)
#include <cuda_runtime.h>
#include <math.h>

#define B_  4
#define S_  2048
#define D_  512
#define H_  8
#define DK_ 64

// Scratch (no cudaMalloc allowed): 4 x 16 MB
__device__ float g_Qh[(size_t)B_ * H_ * S_ * DK_];
__device__ float g_Kh[(size_t)B_ * H_ * S_ * DK_];
__device__ float g_Vh[(size_t)B_ * H_ * S_ * DK_];
__device__ float g_ctx[(size_t)B_ * S_ * D_];

// C = A @ W^T + bias.  A:[8192,512] rowmajor, W:[512,512] rowmajor.
// mode 0: write head-major [B,H,S,DK]; mode 1: write plain [M,N].
// BM=BN=128, BK=8, 256 threads, 8x8 per-thread tile.
__global__ void __launch_bounds__(256) sgemm_nt(const float* __restrict__ A,
                                                const float* __restrict__ W,
                                                const float* __restrict__ bias,
                                                float* __restrict__ C, int mode)
{
    const int K = 512, N = 512;
    __shared__ float As[8][132];
    __shared__ float Bs[8][132];
    const int tid = threadIdx.x;
    const int m0 = blockIdx.y * 128;
    const int n0 = blockIdx.x * 128;
    const int tm = (tid >> 4) * 8;
    const int tn = (tid & 15) * 8;
    const int lr = tid >> 1;          // 0..127
    const int lk = (tid & 1) * 4;     // 0 or 4

    float acc[8][8];
#pragma unroll
    for (int i = 0; i < 8; i++)
#pragma unroll
        for (int j = 0; j < 8; j++) acc[i][j] = 0.f;

    const float* Ag = A + (size_t)(m0 + lr) * K + lk;
    const float* Wg = W + (size_t)(n0 + lr) * K + lk;

    for (int k0 = 0; k0 < K; k0 += 8) {
        float4 a4 = *(const float4*)(Ag + k0);
        float4 b4 = *(const float4*)(Wg + k0);
        __syncthreads();
        As[lk + 0][lr] = a4.x; As[lk + 1][lr] = a4.y;
        As[lk + 2][lr] = a4.z; As[lk + 3][lr] = a4.w;
        Bs[lk + 0][lr] = b4.x; Bs[lk + 1][lr] = b4.y;
        Bs[lk + 2][lr] = b4.z; Bs[lk + 3][lr] = b4.w;
        __syncthreads();
#pragma unroll
        for (int kk = 0; kk < 8; kk++) {
            float ra[8], rb[8];
            *(float4*)(ra)     = *(const float4*)&As[kk][tm];
            *(float4*)(ra + 4) = *(const float4*)&As[kk][tm + 4];
            *(float4*)(rb)     = *(const float4*)&Bs[kk][tn];
            *(float4*)(rb + 4) = *(const float4*)&Bs[kk][tn + 4];
#pragma unroll
            for (int i = 0; i < 8; i++)
#pragma unroll
                for (int j = 0; j < 8; j++)
                    acc[i][j] = fmaf(ra[i], rb[j], acc[i][j]);
        }
    }

#pragma unroll
    for (int i = 0; i < 8; i++) {
        const int m = m0 + tm + i;
        float v[8];
#pragma unroll
        for (int j = 0; j < 8; j++) v[j] = acc[i][j] + bias[n0 + tn + j];
        size_t base;
        if (mode == 0) {
            const int b = m >> 11, s = m & 2047;
            const int n = n0 + tn;
            const int h = n >> 6, dk = n & 63;
            base = ((size_t)(b * H_ + h) * S_ + s) * DK_ + dk;
        } else {
            base = (size_t)m * N + n0 + tn;
        }
        *(float4*)(C + base)     = make_float4(v[0], v[1], v[2], v[3]);
        *(float4*)(C + base + 4) = make_float4(v[4], v[5], v[6], v[7]);
    }
}

// Flash attention: one CTA = (b, h, 64-row q tile). Online softmax.
// Quirk faithful to reference: scores scaled by 1/H (=0.125), mask==0 -> -1e9.
__global__ void __launch_bounds__(256) attn_flash(const float* __restrict__ Qh,
                                                  const float* __restrict__ Kh,
                                                  const float* __restrict__ Vh,
                                                  const int* __restrict__ mask,
                                                  float* __restrict__ ctx)
{
    extern __shared__ float sh[];
    float* Qs = sh;                 // 64*64
    float* Ks = sh + 64 * 64;       // 64*65 (padded; aliased as P after scores)
    float* Vs = Ks + 64 * 65;       // 64*64

    const int tid = threadIdx.x;
    const int ty = tid >> 4, tx = tid & 15;
    const int q0 = blockIdx.x * 64;
    const int h  = blockIdx.y;
    const int b  = blockIdx.z;

    const float* Qg = Qh + ((size_t)(b * H_ + h) * S_ + q0) * DK_;
#pragma unroll
    for (int t = tid; t < 1024; t += 256) {
        const int row = t >> 4, c4 = (t & 15) * 4;
        *(float4*)&Qs[row * 64 + c4] = *(const float4*)(Qg + row * 64 + c4);
    }

    float m_[4], l_[4], acc[4][4];
#pragma unroll
    for (int i = 0; i < 4; i++) {
        m_[i] = -INFINITY; l_[i] = 0.f;
#pragma unroll
        for (int c = 0; c < 4; c++) acc[i][c] = 0.f;
    }

    const size_t headoff = (size_t)(b * H_ + h) * S_ * DK_;
    const size_t mask0 = (size_t)b * S_ * S_;

    for (int kt = 0; kt < S_ / 64; kt++) {
        const int k0 = kt * 64;
        const float* Kg = Kh + headoff + (size_t)k0 * DK_;
        const float* Vg = Vh + headoff + (size_t)k0 * DK_;
        __syncthreads();   // previous iter done with Ks(P)/Vs
#pragma unroll
        for (int t = tid; t < 1024; t += 256) {
            const int row = t >> 4, c4 = (t & 15) * 4;
            const float4 kv = *(const float4*)(Kg + row * 64 + c4);
            Ks[row * 65 + c4 + 0] = kv.x;
            Ks[row * 65 + c4 + 1] = kv.y;
            Ks[row * 65 + c4 + 2] = kv.z;
            Ks[row * 65 + c4 + 3] = kv.w;
            *(float4*)&Vs[row * 64 + c4] = *(const float4*)(Vg + row * 64 + c4);
        }
        __syncthreads();

        float s[4][4];
#pragma unroll
        for (int i = 0; i < 4; i++)
#pragma unroll
            for (int j = 0; j < 4; j++) s[i][j] = 0.f;

#pragma unroll 8
        for (int d = 0; d < 64; d++) {
            float rq[4], rk[4];
#pragma unroll
            for (int i = 0; i < 4; i++) rq[i] = Qs[(ty * 4 + i) * 64 + d];
#pragma unroll
            for (int j = 0; j < 4; j++) rk[j] = Ks[(tx * 4 + j) * 65 + d];
#pragma unroll
            for (int i = 0; i < 4; i++)
#pragma unroll
                for (int j = 0; j < 4; j++)
                    s[i][j] = fmaf(rq[i], rk[j], s[i][j]);
        }

        // scale by 1/H then mask (coalesced int4 from global; L2 serves reuse)
#pragma unroll
        for (int i = 0; i < 4; i++) {
            const int4 mv = *(const int4*)(mask + mask0 +
                              (size_t)(q0 + ty * 4 + i) * S_ + k0 + tx * 4);
            s[i][0] = mv.x ? s[i][0] * 0.125f : -1e9f;
            s[i][1] = mv.y ? s[i][1] * 0.125f : -1e9f;
            s[i][2] = mv.z ? s[i][2] * 0.125f : -1e9f;
            s[i][3] = mv.w ? s[i][3] * 0.125f : -1e9f;
        }

        // online softmax (registers + width-16 shuffles only)
#pragma unroll
        for (int i = 0; i < 4; i++) {
            float mt = fmaxf(fmaxf(s[i][0], s[i][1]), fmaxf(s[i][2], s[i][3]));
#pragma unroll
            for (int off = 8; off > 0; off >>= 1)
                mt = fmaxf(mt, __shfl_xor_sync(0xffffffffu, mt, off, 16));
            const float mn = fmaxf(m_[i], mt);
            const float al = __expf(m_[i] - mn);
            m_[i] = mn;
            float ps = 0.f;
#pragma unroll
            for (int j = 0; j < 4; j++) {
                const float p = __expf(s[i][j] - mn);
                s[i][j] = p; ps += p;
            }
#pragma unroll
            for (int off = 8; off > 0; off >>= 1)
                ps += __shfl_xor_sync(0xffffffffu, ps, off, 16);
            l_[i] = l_[i] * al + ps;
#pragma unroll
            for (int c = 0; c < 4; c++) acc[i][c] *= al;
        }

        __syncthreads();   // everyone done reading Ks
        float* Ps = Ks;
#pragma unroll
        for (int i = 0; i < 4; i++)
#pragma unroll
            for (int j = 0; j < 4; j++)
                Ps[(ty * 4 + i) * 65 + tx * 4 + j] = s[i][j];
        __syncthreads();

#pragma unroll 8
        for (int jj = 0; jj < 64; jj++) {
            float rp[4];
#pragma unroll
            for (int i = 0; i < 4; i++) rp[i] = Ps[(ty * 4 + i) * 65 + jj];
            float rv[4];
            *(float4*)rv = *(const float4*)&Vs[jj * 64 + tx * 4];
#pragma unroll
            for (int i = 0; i < 4; i++)
#pragma unroll
                for (int c = 0; c < 4; c++)
                    acc[i][c] = fmaf(rp[i], rv[c], acc[i][c]);
        }
    }

    // write ctx in [B,S,H,DK] so the O-projection is a plain GEMM
#pragma unroll
    for (int i = 0; i < 4; i++) {
        const float inv = 1.f / l_[i];
        const float4 o = make_float4(acc[i][0] * inv, acc[i][1] * inv,
                                     acc[i][2] * inv, acc[i][3] * inv);
        const size_t idx = ((size_t)(b * S_ + q0 + ty * 4 + i) * H_ + h) * DK_ + tx * 4;
        *(float4*)(g_ctx + idx) = o;
        (void)ctx;
    }
}

extern "C" void kernel_launch(void* const* d_in, const int* in_sizes, int n_in,
                              void* d_out, int out_size)
{
    (void)in_sizes; (void)n_in; (void)out_size;
    const float* q   = (const float*)d_in[0];
    const float* k   = (const float*)d_in[1];
    const float* v   = (const float*)d_in[2];
    const int*  mask = (const int*)d_in[3];
    const float* Wq  = (const float*)d_in[4];
    const float* bq  = (const float*)d_in[5];
    const float* Wk  = (const float*)d_in[6];
    const float* bk  = (const float*)d_in[7];
    const float* Wv  = (const float*)d_in[8];
    const float* bv  = (const float*)d_in[9];
    const float* Wo  = (const float*)d_in[10];
    const float* bo  = (const float*)d_in[11];
    float* out = (float*)d_out;

    float *Qh, *Kh, *Vh, *ctx;
    cudaGetSymbolAddress((void**)&Qh,  g_Qh);
    cudaGetSymbolAddress((void**)&Kh,  g_Kh);
    cudaGetSymbolAddress((void**)&Vh,  g_Vh);
    cudaGetSymbolAddress((void**)&ctx, g_ctx);

    const dim3 gg(4, 64), bb(256);
    sgemm_nt<<<gg, bb>>>(q, Wq, bq, Qh, 0);
    sgemm_nt<<<gg, bb>>>(k, Wk, bk, Kh, 0);
    sgemm_nt<<<gg, bb>>>(v, Wv, bv, Vh, 0);

    const int shmem = (64 * 64 + 64 * 65 + 64 * 64) * sizeof(float);  // 49408 B
    cudaFuncSetAttribute(attn_flash, cudaFuncAttributeMaxDynamicSharedMemorySize, shmem);
    attn_flash<<<dim3(32, 8, 4), 256, shmem>>>(Qh, Kh, Vh, mask, ctx);

    sgemm_nt<<<gg, bb>>>(ctx, Wo, bo, out, 1);
}